// round 1
// baseline (speedup 1.0000x reference)
#include <cuda_runtime.h>

#define OBS_DIM   256
#define HID_DIM   512
#define ACT_DIM   18
#define BATCH     1024
#define ETA       0.01f
#define LAMBDA    0.95f

// Scratch for hidden activations (graph-capture safe: static device global).
__device__ float g_hidden[BATCH * HID_DIM];

// Kernel 1: fused MPN step + Hebbian update.
// Block: 256 threads = 8 warps; handles batch b = blockIdx.y,
// hidden rows [blockIdx.x*8, blockIdx.x*8+8). Each warp owns one (b,h) row:
// the 256-float M row lives in 8 registers/lane, read from HBM exactly once.
__global__ __launch_bounds__(256) void mpn_step_kernel(
    const float* __restrict__ obs,
    const float* __restrict__ M,
    const float* __restrict__ W,
    const float* __restrict__ bh,
    float* __restrict__ newM)
{
    __shared__ float4 xs[OBS_DIM / 4];       // obs row: 64 float4 = 1 KB
    __shared__ float4 ws[8 * OBS_DIM / 4];   // 8 W rows: 512 float4 = 8 KB

    const int b     = blockIdx.y;
    const int hbase = blockIdx.x * 8;
    const int tid   = threadIdx.x;

    if (tid < 64)
        xs[tid] = reinterpret_cast<const float4*>(obs + (size_t)b * OBS_DIM)[tid];
    {
        const float4* Wg = reinterpret_cast<const float4*>(W + (size_t)hbase * OBS_DIM);
        ws[tid]       = Wg[tid];
        ws[tid + 256] = Wg[tid + 256];
    }
    __syncthreads();

    const int warp = tid >> 5;
    const int lane = tid & 31;
    const int h    = hbase + warp;

    const float4* Mrow = reinterpret_cast<const float4*>(
        M + ((size_t)b * HID_DIM + h) * OBS_DIM);

    // Coalesced: 32 lanes x float4 = 512B contiguous per access.
    float4 m0 = Mrow[lane];
    float4 m1 = Mrow[lane + 32];
    float4 x0 = xs[lane];
    float4 x1 = xs[lane + 32];
    float4 w0 = ws[warp * 64 + lane];
    float4 w1 = ws[warp * 64 + lane + 32];

    // sum_o W[h,o] * obs[b,o] * (1 + M[b,h,o])  (base + plastic fused)
    float acc =
        w0.x * x0.x * (1.0f + m0.x) + w0.y * x0.y * (1.0f + m0.y) +
        w0.z * x0.z * (1.0f + m0.z) + w0.w * x0.w * (1.0f + m0.w) +
        w1.x * x1.x * (1.0f + m1.x) + w1.y * x1.y * (1.0f + m1.y) +
        w1.z * x1.z * (1.0f + m1.z) + w1.w * x1.w * (1.0f + m1.w);

    #pragma unroll
    for (int o = 16; o; o >>= 1)
        acc += __shfl_xor_sync(0xffffffffu, acc, o);

    const float hv = tanhf(acc + __ldg(bh + h));
    const float eh = ETA * hv;

    float4 n0, n1;
    n0.x = LAMBDA * m0.x + eh * x0.x;  n0.y = LAMBDA * m0.y + eh * x0.y;
    n0.z = LAMBDA * m0.z + eh * x0.z;  n0.w = LAMBDA * m0.w + eh * x0.w;
    n1.x = LAMBDA * m1.x + eh * x1.x;  n1.y = LAMBDA * m1.y + eh * x1.y;
    n1.z = LAMBDA * m1.z + eh * x1.z;  n1.w = LAMBDA * m1.w + eh * x1.w;

    float4* out = reinterpret_cast<float4*>(
        newM + ((size_t)b * HID_DIM + h) * OBS_DIM);
    out[lane]      = n0;
    out[lane + 32] = n1;

    if (lane == 0)
        g_hidden[(size_t)b * HID_DIM + h] = hv;
}

// Kernel 2: q = hidden @ Wq^T + bq. One warp per batch row; the 512-float
// hidden row is held in 16 regs/lane; Wq (36 KB) stays L2-hot.
__global__ __launch_bounds__(256) void q_head_kernel(
    const float* __restrict__ Wq,
    const float* __restrict__ bq,
    float* __restrict__ q)
{
    const int warp = threadIdx.x >> 5;
    const int lane = threadIdx.x & 31;
    const int b    = blockIdx.x * 8 + warp;

    const float* hrow = g_hidden + (size_t)b * HID_DIM;
    float hr[16];
    #pragma unroll
    for (int k = 0; k < 16; k++)
        hr[k] = hrow[k * 32 + lane];

    #pragma unroll
    for (int a = 0; a < ACT_DIM; a++) {
        float acc = 0.0f;
        #pragma unroll
        for (int k = 0; k < 16; k++)
            acc += hr[k] * __ldg(Wq + (size_t)a * HID_DIM + k * 32 + lane);
        #pragma unroll
        for (int o = 16; o; o >>= 1)
            acc += __shfl_xor_sync(0xffffffffu, acc, o);
        if (lane == 0)
            q[(size_t)b * ACT_DIM + a] = acc + __ldg(bq + a);
    }
}

extern "C" void kernel_launch(void* const* d_in, const int* in_sizes, int n_in,
                              void* d_out, int out_size) {
    const float* obs = (const float*)d_in[0];  // [1024, 256]
    const float* M   = (const float*)d_in[1];  // [1024, 512, 256]
    const float* W   = (const float*)d_in[2];  // [512, 256]
    const float* bh  = (const float*)d_in[3];  // [512]
    const float* Wq  = (const float*)d_in[4];  // [18, 512]
    const float* bq  = (const float*)d_in[5];  // [18]

    float* q    = (float*)d_out;               // [1024, 18]
    float* newM = q + (size_t)BATCH * ACT_DIM; // [1024, 512, 256]

    dim3 grid(HID_DIM / 8, BATCH);
    mpn_step_kernel<<<grid, 256>>>(obs, M, W, bh, newM);
    q_head_kernel<<<BATCH / 8, 256>>>(Wq, bq, q);
}

// round 2
// speedup vs baseline: 1.0518x; 1.0518x over previous
#include <cuda_runtime.h>

#define OBS_DIM   256
#define HID_DIM   512
#define ACT_DIM   18
#define BATCH     1024
#define ETA       0.01f
#define LAMBDA    0.95f
#define BPB       4      // batches per block (W reuse factor)

// Seed q with the bias before the main kernel's atomics accumulate into it.
__global__ void q_init_kernel(const float* __restrict__ bq, float* __restrict__ q) {
    int i = blockIdx.x * blockDim.x + threadIdx.x;
    if (i < BATCH * ACT_DIM) q[i] = bq[i % ACT_DIM];
}

// Fused MPN step + Hebbian update + q-head.
// Block: 256 threads = 8 warps; covers hidden rows [bx*8, bx*8+8) for 4
// consecutive batches. Each warp owns (h, b0..b0+3): the 1KB M row lives in
// 8 regs/lane, read from HBM exactly once, rewritten once. After the warp
// allreduce, lanes 0..17 scatter hv*Wq[a,h] into q via REDG atomics.
__global__ __launch_bounds__(256) void mpn_step_kernel(
    const float* __restrict__ obs,
    const float* __restrict__ M,
    const float* __restrict__ W,
    const float* __restrict__ bh,
    const float* __restrict__ Wq,
    float* __restrict__ newM,
    float* __restrict__ q)
{
    __shared__ float4 xs[BPB * OBS_DIM / 4];   // 4 obs rows: 4 KB
    __shared__ float4 ws[8 * OBS_DIM / 4];     // 8 W rows:   8 KB

    const int b0    = blockIdx.y * BPB;
    const int hbase = blockIdx.x * 8;
    const int tid   = threadIdx.x;

    // 4 obs rows = 256 float4: exactly one per thread.
    {
        const int r = tid >> 6, c = tid & 63;
        xs[tid] = reinterpret_cast<const float4*>(obs + (size_t)(b0 + r) * OBS_DIM)[c];
    }
    // 8 W rows = 512 float4: two per thread.
    {
        const float4* Wg = reinterpret_cast<const float4*>(W + (size_t)hbase * OBS_DIM);
        ws[tid]       = Wg[tid];
        ws[tid + 256] = Wg[tid + 256];
    }
    __syncthreads();

    const int warp = tid >> 5;
    const int lane = tid & 31;
    const int h    = hbase + warp;

    const float  bias = __ldg(bh + h);
    const float  wqv  = (lane < ACT_DIM) ? __ldg(Wq + (size_t)lane * HID_DIM + h) : 0.0f;
    const float4 w0   = ws[warp * 64 + lane];
    const float4 w1   = ws[warp * 64 + lane + 32];

    #pragma unroll
    for (int i = 0; i < BPB; i++) {
        const int b = b0 + i;
        const float4* Mrow = reinterpret_cast<const float4*>(
            M + ((size_t)b * HID_DIM + h) * OBS_DIM);

        // Streaming loads: no reuse, evict-first. 32 lanes x float4 = 512B/access.
        const float4 m0 = __ldcs(Mrow + lane);
        const float4 m1 = __ldcs(Mrow + lane + 32);
        const float4 x0 = xs[i * 64 + lane];
        const float4 x1 = xs[i * 64 + lane + 32];

        // sum_o W[h,o] * obs[b,o] * (1 + M[b,h,o])
        float acc =
            w0.x * x0.x * (1.0f + m0.x) + w0.y * x0.y * (1.0f + m0.y) +
            w0.z * x0.z * (1.0f + m0.z) + w0.w * x0.w * (1.0f + m0.w) +
            w1.x * x1.x * (1.0f + m1.x) + w1.y * x1.y * (1.0f + m1.y) +
            w1.z * x1.z * (1.0f + m1.z) + w1.w * x1.w * (1.0f + m1.w);

        #pragma unroll
        for (int o = 16; o; o >>= 1)
            acc += __shfl_xor_sync(0xffffffffu, acc, o);   // allreduce: hv in all lanes

        const float hv = tanhf(acc + bias);
        const float eh = ETA * hv;

        float4 n0, n1;
        n0.x = LAMBDA * m0.x + eh * x0.x;  n0.y = LAMBDA * m0.y + eh * x0.y;
        n0.z = LAMBDA * m0.z + eh * x0.z;  n0.w = LAMBDA * m0.w + eh * x0.w;
        n1.x = LAMBDA * m1.x + eh * x1.x;  n1.y = LAMBDA * m1.y + eh * x1.y;
        n1.z = LAMBDA * m1.z + eh * x1.z;  n1.w = LAMBDA * m1.w + eh * x1.w;

        float4* out = reinterpret_cast<float4*>(
            newM + ((size_t)b * HID_DIM + h) * OBS_DIM);
        __stcs(out + lane,      n0);
        __stcs(out + lane + 32, n1);

        // q[b, a] += hv * Wq[a, h]  — fire-and-forget REDG, one per lane<18.
        if (lane < ACT_DIM)
            atomicAdd(q + (size_t)b * ACT_DIM + lane, hv * wqv);
    }
}

extern "C" void kernel_launch(void* const* d_in, const int* in_sizes, int n_in,
                              void* d_out, int out_size) {
    const float* obs = (const float*)d_in[0];  // [1024, 256]
    const float* M   = (const float*)d_in[1];  // [1024, 512, 256]
    const float* W   = (const float*)d_in[2];  // [512, 256]
    const float* bh  = (const float*)d_in[3];  // [512]
    const float* Wq  = (const float*)d_in[4];  // [18, 512]
    const float* bq  = (const float*)d_in[5];  // [18]

    float* q    = (float*)d_out;               // [1024, 18]
    float* newM = q + (size_t)BATCH * ACT_DIM; // [1024, 512, 256]

    q_init_kernel<<<(BATCH * ACT_DIM + 255) / 256, 256>>>(bq, q);

    dim3 grid(HID_DIM / 8, BATCH / BPB);
    mpn_step_kernel<<<grid, 256>>>(obs, M, W, bh, Wq, newM, q);
}

// round 3
// speedup vs baseline: 1.1448x; 1.0884x over previous
#include <cuda_runtime.h>

#define OBS_DIM   256
#define HID_DIM   512
#define ACT_DIM   18
#define BATCH     1024
#define ETA       0.01f
#define LAMBDA    0.95f
#define BPB       8      // batches per block

// Seed q with the bias before the main kernel's atomics accumulate into it.
__global__ void q_init_kernel(const float* __restrict__ bq, float* __restrict__ q) {
    int i = blockIdx.x * blockDim.x + threadIdx.x;
    if (i < BATCH * ACT_DIM) q[i] = bq[i % ACT_DIM];
}

// Fused MPN step + Hebbian update + q-head.
// Block: 8 warps; hidden rows [bx*8, bx*8+8) x 8 consecutive batches.
// Each warp owns one h row: W row in 8 regs (loop-invariant), each batch's
// 1KB M row in 8 regs read from HBM exactly once. M loads for iteration i+1
// are issued before iteration i's reduce/tanh/store chain (prefetch), so a
// 1KB read stays in flight per warp at all times. Per-h q contributions are
// reduced through smem so only 18 global REDs leave per (block, batch).
__global__ __launch_bounds__(256, 6) void mpn_step_kernel(
    const float* __restrict__ obs,
    const float* __restrict__ M,
    const float* __restrict__ W,
    const float* __restrict__ bh,
    const float* __restrict__ Wq,
    float* __restrict__ newM,
    float* __restrict__ q)
{
    __shared__ float4 xs[BPB * OBS_DIM / 4];  // 8 obs rows: 8 KB
    __shared__ float  hsh[BPB][8];            // hv per (batch, warp)

    const int b0    = blockIdx.y * BPB;
    const int hbase = blockIdx.x * 8;
    const int tid   = threadIdx.x;

    // 8 obs rows = 512 float4: two per thread.
    {
        const float4* og = reinterpret_cast<const float4*>(obs + (size_t)b0 * OBS_DIM);
        xs[tid]       = og[tid];
        xs[tid + 256] = og[tid + 256];
    }
    __syncthreads();

    const int warp = tid >> 5;
    const int lane = tid & 31;
    const int h    = hbase + warp;

    const float bias = __ldg(bh + h);
    const float4* wp = reinterpret_cast<const float4*>(W + (size_t)h * OBS_DIM);
    const float4 w0  = __ldg(wp + lane);     // coalesced, L2-hot
    const float4 w1  = __ldg(wp + lane + 32);

    const size_t bstride = (size_t)HID_DIM * OBS_DIM / 4;  // float4 units
    const float4* Mrow = reinterpret_cast<const float4*>(M)
                       + ((size_t)b0 * HID_DIM + h) * (OBS_DIM / 4);
    float4* Orow = reinterpret_cast<float4*>(newM)
                 + ((size_t)b0 * HID_DIM + h) * (OBS_DIM / 4);

    // Prologue: loads for iteration 0.
    float4 m0 = __ldcs(Mrow + lane);
    float4 m1 = __ldcs(Mrow + lane + 32);

    #pragma unroll
    for (int i = 0; i < BPB; i++) {
        // Prefetch next batch's M row before touching the dependency chain.
        float4 p0, p1;
        if (i + 1 < BPB) {
            const float4* Mn = Mrow + (size_t)(i + 1) * bstride;
            p0 = __ldcs(Mn + lane);
            p1 = __ldcs(Mn + lane + 32);
        }

        const float4 x0 = xs[i * 64 + lane];
        const float4 x1 = xs[i * 64 + lane + 32];

        // sum_o W[h,o] * obs[b,o] * (1 + M[b,h,o])
        float acc =
            w0.x * x0.x * (1.0f + m0.x) + w0.y * x0.y * (1.0f + m0.y) +
            w0.z * x0.z * (1.0f + m0.z) + w0.w * x0.w * (1.0f + m0.w) +
            w1.x * x1.x * (1.0f + m1.x) + w1.y * x1.y * (1.0f + m1.y) +
            w1.z * x1.z * (1.0f + m1.z) + w1.w * x1.w * (1.0f + m1.w);

        #pragma unroll
        for (int o = 16; o; o >>= 1)
            acc += __shfl_xor_sync(0xffffffffu, acc, o);

        const float hv = tanhf(acc + bias);
        const float eh = ETA * hv;

        float4 n0, n1;
        n0.x = LAMBDA * m0.x + eh * x0.x;  n0.y = LAMBDA * m0.y + eh * x0.y;
        n0.z = LAMBDA * m0.z + eh * x0.z;  n0.w = LAMBDA * m0.w + eh * x0.w;
        n1.x = LAMBDA * m1.x + eh * x1.x;  n1.y = LAMBDA * m1.y + eh * x1.y;
        n1.z = LAMBDA * m1.z + eh * x1.z;  n1.w = LAMBDA * m1.w + eh * x1.w;

        float4* Ob = Orow + (size_t)i * bstride;
        __stcs(Ob + lane,      n0);
        __stcs(Ob + lane + 32, n1);

        if (lane == 0) hsh[i][warp] = hv;

        m0 = p0; m1 = p1;
    }

    __syncthreads();

    // q-head epilogue: warp 0 reduces the block's 8 h-rows, 18 REDs per batch.
    if (warp == 0 && lane < ACT_DIM) {
        const float4* wq = reinterpret_cast<const float4*>(
            Wq + (size_t)lane * HID_DIM + hbase);
        const float4 a0 = __ldg(wq);      // Wq[lane, hbase..hbase+3]
        const float4 a1 = __ldg(wq + 1);  // Wq[lane, hbase+4..hbase+7]
        #pragma unroll
        for (int i = 0; i < BPB; i++) {
            float qv = a0.x * hsh[i][0] + a0.y * hsh[i][1]
                     + a0.z * hsh[i][2] + a0.w * hsh[i][3]
                     + a1.x * hsh[i][4] + a1.y * hsh[i][5]
                     + a1.z * hsh[i][6] + a1.w * hsh[i][7];
            atomicAdd(q + (size_t)(b0 + i) * ACT_DIM + lane, qv);
        }
    }
}

extern "C" void kernel_launch(void* const* d_in, const int* in_sizes, int n_in,
                              void* d_out, int out_size) {
    const float* obs = (const float*)d_in[0];  // [1024, 256]
    const float* M   = (const float*)d_in[1];  // [1024, 512, 256]
    const float* W   = (const float*)d_in[2];  // [512, 256]
    const float* bh  = (const float*)d_in[3];  // [512]
    const float* Wq  = (const float*)d_in[4];  // [18, 512]
    const float* bq  = (const float*)d_in[5];  // [18]

    float* q    = (float*)d_out;               // [1024, 18]
    float* newM = q + (size_t)BATCH * ACT_DIM; // [1024, 512, 256]

    q_init_kernel<<<(BATCH * ACT_DIM + 255) / 256, 256>>>(bq, q);

    dim3 grid(HID_DIM / 8, BATCH / BPB);
    mpn_step_kernel<<<grid, 256>>>(obs, M, W, bh, Wq, newM, q);
}